// round 1
// baseline (speedup 1.0000x reference)
#include <cuda_runtime.h>
#include <cstdint>

// Problem constants (fixed shapes per the dataset)
#define MAX_ATOMS 8000
#define NF 32          // nf_in == nf_out == 32
#define ND 16          // n_dist
#define WF_STRIDE 512  // ND*NF, laid out [j][o][d] (o-major, d contiguous)

// Scratch (static __device__ allocations are allowed; cudaMalloc is not)
__device__ float g_WF[(size_t)MAX_ATOMS * WF_STRIDE];
__device__ int   g_seg[MAX_ATOMS + 1];

// ---------------------------------------------------------------------------
// K0: segment offsets from sorted pair_first.  g_seg[a] = first p with pf[p]>=a
// ---------------------------------------------------------------------------
__global__ void seg_kernel(const int* __restrict__ pf, int n_pairs, int n_atoms) {
    int p = blockIdx.x * blockDim.x + threadIdx.x;
    if (p >= n_pairs) return;
    int a = pf[p];
    int prev = (p == 0) ? -1 : pf[p - 1];
    for (int x = prev + 1; x <= a; ++x) g_seg[x] = p;
    if (p == n_pairs - 1)
        for (int x = a + 1; x <= n_atoms; ++x) g_seg[x] = n_pairs;
}

// ---------------------------------------------------------------------------
// K1: WF[j,o,d] = sum_f int_weights[d,o,f] * feat[j,f]
// Warp processes 4 atoms at once so each smem W read feeds 4 FMAs (FMA-bound).
// Wt in smem transposed+padded: Wt[(d*32+f)*33 + o]  (conflict-free both ways)
// ---------------------------------------------------------------------------
extern __shared__ float k1smem[];

__global__ __launch_bounds__(256) void wf_kernel(
    const float* __restrict__ feat, const float* __restrict__ W, int n_atoms)
{
    float* Wt     = k1smem;                  // 16*32*33 = 16896 floats
    float* featsm = k1smem + 16 * 32 * 33;   // 8 warps * 4 atoms * 32 = 1024

    int tid = threadIdx.x;
    // Transpose W[d][o][f] -> Wt[d][f][o] (coalesced LDG, conflict-free STS via pad-33)
    for (int idx = tid; idx < 16384; idx += 256) {
        int d = idx >> 10, o = (idx >> 5) & 31, f = idx & 31;
        Wt[(d * 32 + f) * 33 + o] = W[idx];
    }
    __syncthreads();

    int lane = tid & 31, w = tid >> 5;
    int warp_global = blockIdx.x * 8 + w;
    int stride = gridDim.x * 8 * 4;
    float* fb = featsm + w * 128;

    for (int j0 = warp_global * 4; j0 < n_atoms; j0 += stride) {
        #pragma unroll
        for (int a = 0; a < 4; ++a) {
            int j = j0 + a;
            fb[a * 32 + lane] = (j < n_atoms) ? feat[j * 32 + lane] : 0.f;
        }
        __syncwarp();

        float acc[4][16];
        #pragma unroll
        for (int a = 0; a < 4; ++a)
            #pragma unroll
            for (int d = 0; d < 16; ++d) acc[a][d] = 0.f;

        #pragma unroll 4
        for (int f = 0; f < 32; ++f) {
            float fv0 = fb[0 * 32 + f];
            float fv1 = fb[1 * 32 + f];
            float fv2 = fb[2 * 32 + f];
            float fv3 = fb[3 * 32 + f];
            #pragma unroll
            for (int d = 0; d < 16; ++d) {
                float wv = Wt[(d * 32 + f) * 33 + lane];
                acc[0][d] += fv0 * wv;
                acc[1][d] += fv1 * wv;
                acc[2][d] += fv2 * wv;
                acc[3][d] += fv3 * wv;
            }
        }

        #pragma unroll
        for (int a = 0; a < 4; ++a) {
            int j = j0 + a;
            if (j >= n_atoms) break;
            float4* dst = (float4*)(g_WF + (size_t)j * WF_STRIDE + lane * ND);
            #pragma unroll
            for (int d4 = 0; d4 < 4; ++d4)
                dst[d4] = make_float4(acc[a][d4 * 4 + 0], acc[a][d4 * 4 + 1],
                                      acc[a][d4 * 4 + 2], acc[a][d4 * 4 + 3]);
        }
        __syncwarp();
    }
}

// ---------------------------------------------------------------------------
// K2: warp-per-atom. Pair loop -> tf[c] in regs -> invariants -> GroupNorm
// (warp butterflies, two-pass var) -> mixing + self-interaction epilogue.
// ---------------------------------------------------------------------------
__global__ __launch_bounds__(256) void main_kernel(
    const float* __restrict__ feat,  const float* __restrict__ rhats,
    const float* __restrict__ dist,  const float* __restrict__ selfw,
    const float* __restrict__ selfb, const float* __restrict__ mixw,
    const float* __restrict__ gnw,   const float* __restrict__ gnb,
    const float* __restrict__ mu,    const float* __restrict__ sig,
    const int*   __restrict__ psec,  float* __restrict__ out, int n_atoms)
{
    __shared__ float Mws[64 * 32];   // mixing weights, row-major (k, o_out)
    __shared__ float sWt[32 * 32];   // selfint_w transposed: [f][o]
    __shared__ float gw[64], gb[64];
    __shared__ float nv[8][64];

    int tid = threadIdx.x;
    for (int i = tid; i < 2048; i += 256) Mws[i] = mixw[i];
    for (int i = tid; i < 1024; i += 256) {
        int o = i >> 5, f = i & 31;
        sWt[f * 32 + o] = selfw[i];
    }
    if (tid < 64) { gw[tid] = gnw[tid]; gb[tid] = gnb[tid]; }
    __syncthreads();

    int lane = tid & 31, w = tid >> 5;
    int a = blockIdx.x * 8 + w;
    if (a >= n_atoms) return;

    int dd = lane & 15;
    float mu_l = mu[dd];
    float isg  = 1.0f / sig[dd];

    float tf0 = 0.f, tf1 = 0.f, tf2 = 0.f, tf3 = 0.f;
    int p0 = g_seg[a], p1 = g_seg[a + 1];

    for (int p = p0; p < p1; ++p) {
        int j = psec[p];
        float dp = dist[p];
        float4 rh = ((const float4*)rhats)[p];

        float invd = 1.0f / dp;
        float t = (invd - mu_l) * isg;
        float cs = __cosf(dp * 0.241660973353061f);   // 0.5*pi/6.5
        float cut = (dp < 6.5f) ? cs * cs : 0.f;
        float sval = __expf(-0.5f * t * t) * cut;

        float s[16];
        #pragma unroll
        for (int d = 0; d < 16; ++d) s[d] = __shfl_sync(0xffffffffu, sval, d);

        const float4* wf = (const float4*)(g_WF + (size_t)j * WF_STRIDE + lane * ND);
        float q = 0.f;
        #pragma unroll
        for (int d4 = 0; d4 < 4; ++d4) {
            float4 v = wf[d4];
            q += s[d4 * 4 + 0] * v.x + s[d4 * 4 + 1] * v.y
               + s[d4 * 4 + 2] * v.z + s[d4 * 4 + 3] * v.w;
        }
        tf0 += rh.x * q; tf1 += rh.y * q; tf2 += rh.z * q; tf3 += rh.w * q;
    }

    // Invariants: l=0 scalar, |l=1 vector|^2
    float i0 = tf0;
    float i1 = tf1 * tf1 + tf2 * tf2 + tf3 * tf3;

    // GroupNorm over the 32 channels of each invariant group (two-pass)
    float m0 = i0, m1 = i1;
    #pragma unroll
    for (int off = 16; off; off >>= 1) {
        m0 += __shfl_xor_sync(0xffffffffu, m0, off);
        m1 += __shfl_xor_sync(0xffffffffu, m1, off);
    }
    m0 *= (1.f / 32.f); m1 *= (1.f / 32.f);
    float d0 = i0 - m0, d1 = i1 - m1;
    float v0 = d0 * d0, v1 = d1 * d1;
    #pragma unroll
    for (int off = 16; off; off >>= 1) {
        v0 += __shfl_xor_sync(0xffffffffu, v0, off);
        v1 += __shfl_xor_sync(0xffffffffu, v1, off);
    }
    v0 *= (1.f / 32.f); v1 *= (1.f / 32.f);
    float r0 = rsqrtf(v0 + 1e-5f), r1 = rsqrtf(v1 + 1e-5f);
    float xn0 = d0 * r0 * gw[lane]      + gb[lane];
    float xn1 = d1 * r1 * gw[32 + lane] + gb[32 + lane];

    // norm_inv flat index = o*2 + i
    ((float2*)nv[w])[lane] = make_float2(xn0, xn1);
    __syncwarp();

    // self interaction: out += feat[a] @ selfw.T + b
    float fv = feat[a * 32 + lane];
    float acc = selfb[lane];
    #pragma unroll
    for (int f = 0; f < 32; ++f)
        acc += __shfl_sync(0xffffffffu, fv, f) * sWt[f * 32 + lane];

    // mixing: acc += sum_k nv[k] * Mw[k, lane]
    #pragma unroll 8
    for (int k = 0; k < 64; ++k)
        acc += nv[w][k] * Mws[k * 32 + lane];

    out[a * 32 + lane] = acc;
}

// ---------------------------------------------------------------------------
extern "C" void kernel_launch(void* const* d_in, const int* in_sizes, int n_in,
                              void* d_out, int out_size)
{
    const float* in_features = (const float*)d_in[0];
    const float* rhats       = (const float*)d_in[1];
    const float* dist        = (const float*)d_in[2];
    const float* int_w       = (const float*)d_in[3];
    const float* selfw       = (const float*)d_in[4];
    const float* selfb       = (const float*)d_in[5];
    const float* mixw        = (const float*)d_in[6];
    const float* gnw         = (const float*)d_in[7];
    const float* gnb         = (const float*)d_in[8];
    const float* mu          = (const float*)d_in[9];
    const float* sig         = (const float*)d_in[10];
    const int*   pfirst      = (const int*)d_in[11];
    const int*   psec        = (const int*)d_in[12];
    float* out = (float*)d_out;

    int n_atoms = in_sizes[0] / NF;
    int n_pairs = in_sizes[2];

    // K0: segment offsets
    seg_kernel<<<(n_pairs + 255) / 256, 256>>>(pfirst, n_pairs, n_atoms);

    // K1: WF precompute (dynamic smem > 48KB)
    int k1smem_bytes = (16 * 32 * 33 + 8 * 4 * 32) * (int)sizeof(float);
    static bool attr_set = false;
    cudaFuncSetAttribute(wf_kernel, cudaFuncAttributeMaxDynamicSharedMemorySize,
                         k1smem_bytes);
    (void)attr_set;
    int k1_blocks = (n_atoms + 31) / 32;   // 8 warps * 4 atoms per block
    wf_kernel<<<k1_blocks, 256, k1smem_bytes>>>(in_features, int_w, n_atoms);

    // K2: main fused kernel (warp per atom)
    int k2_blocks = (n_atoms + 7) / 8;
    main_kernel<<<k2_blocks, 256>>>(in_features, rhats, dist, selfw, selfb,
                                    mixw, gnw, gnb, mu, sig, psec, out, n_atoms);
}

// round 2
// speedup vs baseline: 1.3658x; 1.3658x over previous
#include <cuda_runtime.h>
#include <cuda_fp16.h>
#include <cstdint>

// Problem constants (fixed shapes per the dataset)
#define MAX_ATOMS 8000
#define MAX_PAIRS 80000
#define NF 32          // nf_in == nf_out == 32
#define ND 16          // n_dist
#define WF_STRIDE 512  // ND*NF halfs, laid out [j][o][d] (o-major, d contiguous)
#define K1_BLOCKS 250  // 250 blocks * 8 warps * 4 atoms = 8000 atoms

// Scratch (static __device__ allocations are allowed; cudaMalloc is not)
__device__ __half g_WF[(size_t)MAX_ATOMS * WF_STRIDE];      // 8 MB
__device__ float  g_sense[(size_t)MAX_PAIRS * ND];          // 5 MB
__device__ int    g_seg[MAX_ATOMS + 1];

// ---------------------------------------------------------------------------
// Prep kernel (fused):
//   blocks [0, K1_BLOCKS):     WF[j,o,d] = sum_f int_weights[d,o,f]*feat[j,f]
//   blocks [K1_BLOCKS, ...):   seg offsets from sorted pair_first
//                              + sense[p,d] (inverse-dist Gaussians * cutoff)
// ---------------------------------------------------------------------------
extern __shared__ float k1smem[];

__global__ __launch_bounds__(256) void prep_kernel(
    const float* __restrict__ feat, const float* __restrict__ W,
    const float* __restrict__ dist, const int* __restrict__ pf,
    const float* __restrict__ mu,   const float* __restrict__ sig,
    int n_atoms, int n_pairs)
{
    if (blockIdx.x >= K1_BLOCKS) {
        // ---- seg + sense: one thread per pair ----
        int p = (blockIdx.x - K1_BLOCKS) * 256 + threadIdx.x;
        if (p >= n_pairs) return;
        int a = pf[p];
        int prev = (p == 0) ? -1 : pf[p - 1];
        for (int x = prev + 1; x <= a; ++x) g_seg[x] = p;
        if (p == n_pairs - 1)
            for (int x = a + 1; x <= n_atoms; ++x) g_seg[x] = n_pairs;

        float dp = dist[p];
        float invd = 1.0f / dp;
        float cs = __cosf(dp * 0.241660973353061f);   // 0.5*pi/6.5
        float cut = (dp < 6.5f) ? cs * cs : 0.f;
        float sv[16];
        #pragma unroll
        for (int d = 0; d < 16; ++d) {
            float t = (invd - __ldg(mu + d)) / __ldg(sig + d);
            sv[d] = __expf(-0.5f * t * t) * cut;
        }
        float4* dst = (float4*)(g_sense + (size_t)p * ND);
        #pragma unroll
        for (int d4 = 0; d4 < 4; ++d4)
            dst[d4] = make_float4(sv[d4 * 4], sv[d4 * 4 + 1],
                                  sv[d4 * 4 + 2], sv[d4 * 4 + 3]);
        return;
    }

    // ---- WF GEMM part ----
    float* Wt     = k1smem;                  // 16*32*33 = 16896 floats
    float* featsm = k1smem + 16 * 32 * 33;   // 8 warps * 4 atoms * 32 = 1024

    int tid = threadIdx.x;
    // Transpose W[d][o][f] -> Wt[d][f][o] (coalesced LDG, conflict-free pad-33)
    for (int idx = tid; idx < 16384; idx += 256) {
        int d = idx >> 10, o = (idx >> 5) & 31, f = idx & 31;
        Wt[(d * 32 + f) * 33 + o] = W[idx];
    }
    __syncthreads();

    int lane = tid & 31, w = tid >> 5;
    int warp_global = blockIdx.x * 8 + w;
    int stride = K1_BLOCKS * 8 * 4;
    float* fb = featsm + w * 128;

    for (int j0 = warp_global * 4; j0 < n_atoms; j0 += stride) {
        #pragma unroll
        for (int a = 0; a < 4; ++a) {
            int j = j0 + a;
            fb[a * 32 + lane] = (j < n_atoms) ? feat[j * 32 + lane] : 0.f;
        }
        __syncwarp();

        float acc[4][16];
        #pragma unroll
        for (int a = 0; a < 4; ++a)
            #pragma unroll
            for (int d = 0; d < 16; ++d) acc[a][d] = 0.f;

        #pragma unroll 4
        for (int f = 0; f < 32; ++f) {
            float fv0 = fb[0 * 32 + f];
            float fv1 = fb[1 * 32 + f];
            float fv2 = fb[2 * 32 + f];
            float fv3 = fb[3 * 32 + f];
            #pragma unroll
            for (int d = 0; d < 16; ++d) {
                float wv = Wt[(d * 32 + f) * 33 + lane];
                acc[0][d] += fv0 * wv;
                acc[1][d] += fv1 * wv;
                acc[2][d] += fv2 * wv;
                acc[3][d] += fv3 * wv;
            }
        }

        #pragma unroll
        for (int a = 0; a < 4; ++a) {
            int j = j0 + a;
            if (j >= n_atoms) break;
            __half2 hv[8];
            #pragma unroll
            for (int d2 = 0; d2 < 8; ++d2)
                hv[d2] = __floats2half2_rn(acc[a][2 * d2], acc[a][2 * d2 + 1]);
            uint4* dst = (uint4*)(g_WF + (size_t)j * WF_STRIDE + lane * ND);
            dst[0] = *(uint4*)&hv[0];
            dst[1] = *(uint4*)&hv[4];
        }
        __syncwarp();
    }
}

// ---------------------------------------------------------------------------
// K2: warp-per-atom, 2x pair unroll. tf[c] in regs -> invariants -> GroupNorm
// (warp butterflies) -> mixing + self-interaction epilogue.
// ---------------------------------------------------------------------------
__device__ __forceinline__ float pair_q(int j, int lane, const float4* sp)
{
    float4 s0 = sp[0], s1 = sp[1], s2 = sp[2], s3 = sp[3];
    const uint4* wf = (const uint4*)(g_WF + (size_t)j * WF_STRIDE + lane * ND);
    uint4 w0 = wf[0], w1 = wf[1];
    const __half2* h0 = (const __half2*)&w0;
    const __half2* h1 = (const __half2*)&w1;
    float2 f0 = __half22float2(h0[0]);
    float2 f1 = __half22float2(h0[1]);
    float2 f2 = __half22float2(h0[2]);
    float2 f3 = __half22float2(h0[3]);
    float2 f4 = __half22float2(h1[0]);
    float2 f5 = __half22float2(h1[1]);
    float2 f6 = __half22float2(h1[2]);
    float2 f7 = __half22float2(h1[3]);
    float q = 0.f;
    q += s0.x * f0.x + s0.y * f0.y + s0.z * f1.x + s0.w * f1.y;
    q += s1.x * f2.x + s1.y * f2.y + s1.z * f3.x + s1.w * f3.y;
    q += s2.x * f4.x + s2.y * f4.y + s2.z * f5.x + s2.w * f5.y;
    q += s3.x * f6.x + s3.y * f6.y + s3.z * f7.x + s3.w * f7.y;
    return q;
}

__global__ __launch_bounds__(256) void main_kernel(
    const float* __restrict__ feat,  const float* __restrict__ rhats,
    const float* __restrict__ selfw, const float* __restrict__ selfb,
    const float* __restrict__ mixw,  const float* __restrict__ gnw,
    const float* __restrict__ gnb,   const int* __restrict__ psec,
    float* __restrict__ out, int n_atoms)
{
    __shared__ float Mws[64 * 32];   // mixing weights, row-major (k, o_out)
    __shared__ float sWt[32 * 32];   // selfint_w transposed: [f][o]
    __shared__ float gw[64], gb[64];
    __shared__ float nv[8][64];

    int tid = threadIdx.x;
    for (int i = tid; i < 2048; i += 256) Mws[i] = mixw[i];
    for (int i = tid; i < 1024; i += 256) {
        int o = i >> 5, f = i & 31;
        sWt[f * 32 + o] = selfw[i];
    }
    if (tid < 64) { gw[tid] = gnw[tid]; gb[tid] = gnb[tid]; }
    __syncthreads();

    int lane = tid & 31, w = tid >> 5;
    int a = blockIdx.x * 8 + w;
    if (a >= n_atoms) return;

    float tf0 = 0.f, tf1 = 0.f, tf2 = 0.f, tf3 = 0.f;
    int p0 = g_seg[a], p1 = g_seg[a + 1];

    int p = p0;
    for (; p + 1 < p1; p += 2) {
        int ja = psec[p], jb = psec[p + 1];
        float4 rha = ((const float4*)rhats)[p];
        float4 rhb = ((const float4*)rhats)[p + 1];
        float qa = pair_q(ja, lane, (const float4*)(g_sense + (size_t)p * ND));
        float qb = pair_q(jb, lane, (const float4*)(g_sense + (size_t)(p + 1) * ND));
        tf0 += rha.x * qa + rhb.x * qb;
        tf1 += rha.y * qa + rhb.y * qb;
        tf2 += rha.z * qa + rhb.z * qb;
        tf3 += rha.w * qa + rhb.w * qb;
    }
    if (p < p1) {
        int j = psec[p];
        float4 rh = ((const float4*)rhats)[p];
        float q = pair_q(j, lane, (const float4*)(g_sense + (size_t)p * ND));
        tf0 += rh.x * q; tf1 += rh.y * q; tf2 += rh.z * q; tf3 += rh.w * q;
    }

    // Invariants: l=0 scalar, |l=1 vector|^2
    float i0 = tf0;
    float i1 = tf1 * tf1 + tf2 * tf2 + tf3 * tf3;

    // GroupNorm over 32 channels per invariant group (two-pass, warp butterflies)
    float m0 = i0, m1 = i1;
    #pragma unroll
    for (int off = 16; off; off >>= 1) {
        m0 += __shfl_xor_sync(0xffffffffu, m0, off);
        m1 += __shfl_xor_sync(0xffffffffu, m1, off);
    }
    m0 *= (1.f / 32.f); m1 *= (1.f / 32.f);
    float d0 = i0 - m0, d1 = i1 - m1;
    float v0 = d0 * d0, v1 = d1 * d1;
    #pragma unroll
    for (int off = 16; off; off >>= 1) {
        v0 += __shfl_xor_sync(0xffffffffu, v0, off);
        v1 += __shfl_xor_sync(0xffffffffu, v1, off);
    }
    v0 *= (1.f / 32.f); v1 *= (1.f / 32.f);
    float r0 = rsqrtf(v0 + 1e-5f), r1 = rsqrtf(v1 + 1e-5f);
    float xn0 = d0 * r0 * gw[lane]      + gb[lane];
    float xn1 = d1 * r1 * gw[32 + lane] + gb[32 + lane];

    // norm_inv flat index = o*2 + i
    ((float2*)nv[w])[lane] = make_float2(xn0, xn1);
    __syncwarp();

    // self interaction: out += feat[a] @ selfw.T + b
    float fv = feat[a * 32 + lane];
    float acc = selfb[lane];
    #pragma unroll
    for (int f = 0; f < 32; ++f)
        acc += __shfl_sync(0xffffffffu, fv, f) * sWt[f * 32 + lane];

    // mixing: acc += sum_k nv[k] * Mw[k, lane]
    #pragma unroll 8
    for (int k = 0; k < 64; ++k)
        acc += nv[w][k] * Mws[k * 32 + lane];

    out[a * 32 + lane] = acc;
}

// ---------------------------------------------------------------------------
extern "C" void kernel_launch(void* const* d_in, const int* in_sizes, int n_in,
                              void* d_out, int out_size)
{
    const float* in_features = (const float*)d_in[0];
    const float* rhats       = (const float*)d_in[1];
    const float* dist        = (const float*)d_in[2];
    const float* int_w       = (const float*)d_in[3];
    const float* selfw       = (const float*)d_in[4];
    const float* selfb       = (const float*)d_in[5];
    const float* mixw        = (const float*)d_in[6];
    const float* gnw         = (const float*)d_in[7];
    const float* gnb         = (const float*)d_in[8];
    const float* mu          = (const float*)d_in[9];
    const float* sig         = (const float*)d_in[10];
    const int*   pfirst      = (const int*)d_in[11];
    const int*   psec        = (const int*)d_in[12];
    float* out = (float*)d_out;

    int n_atoms = in_sizes[0] / NF;
    int n_pairs = in_sizes[2];

    // Fused prep: K1 WF blocks + (seg + sense) blocks
    int seg_blocks = (n_pairs + 255) / 256;
    int k1smem_bytes = (16 * 32 * 33 + 8 * 4 * 32) * (int)sizeof(float);
    cudaFuncSetAttribute(prep_kernel, cudaFuncAttributeMaxDynamicSharedMemorySize,
                         k1smem_bytes);
    prep_kernel<<<K1_BLOCKS + seg_blocks, 256, k1smem_bytes>>>(
        in_features, int_w, dist, pfirst, mu, sig, n_atoms, n_pairs);

    // Main fused kernel (warp per atom)
    int k2_blocks = (n_atoms + 7) / 8;
    main_kernel<<<k2_blocks, 256>>>(in_features, rhats, selfw, selfb,
                                    mixw, gnw, gnb, psec, out, n_atoms);
}